// round 9
// baseline (speedup 1.0000x reference)
#include <cuda_runtime.h>
#include <cuda_bf16.h>

// ElasticEnergyLossWithJacobian — GB300 sm_103a, round 6.
// x-sweep, register window for dX, double-buffered smem plane (6 y-rows incl.
// halos) for dY/dZ. Fused last-block final reduction (single kernel launch).

#define DD 192
#define S1 192
#define S2 (192*192)
#define S3 (192*192*192)
#define XSEG 16
#define NSEG (DD / XSEG)          // 12
#define NBLK (2 * NSEG * 48)      // 1152
#define NVOX (2.0*192.0*192.0*192.0)

__device__ double g_part[NBLK];
__device__ unsigned int g_cnt = 0;   // atomicInc wraps back to 0 every launch

__device__ __forceinline__ float robust01(float x) {
    float a = fabsf(x);
    return (a <= 0.01f) ? 0.5f * x * x : 0.01f * (a - 0.005f);
}

__global__ __launch_bounds__(192) void elastic_kernel(const float* __restrict__ df,
                                                      float* __restrict__ out) {
    // smem: double-buffered plane, 3 comps x 6 y-rows (1 halo each side) x 192 z
    __shared__ float sp[2][3][6][192];
    __shared__ double ws[6];
    __shared__ bool is_last;

    int bid   = blockIdx.x;
    int b     = bid / (NSEG * 48);
    int r     = bid % (NSEG * 48);
    int xseg  = r / 48;
    int ytile = r % 48;
    int yt = threadIdx.y;               // 0..3
    int zt = threadIdx.x;               // 0..47
    int y  = ytile * 4 + yt;
    int z4 = zt * 4;
    int x0 = xseg * XSEG;

    const float* base = df + (size_t)b * 3 * S3;
    int offyz = y * S1 + z4;
    int yhm = max(ytile * 4 - 1, 0);        // global row for smem halo row 0
    int yhp = min(ytile * 4 + 4, DD - 1);   // global row for smem halo row 5
    int hoff_m = yhm * S1 + z4;
    int hoff_p = yhp * S1 + z4;

    float sy = (y == 0 || y == DD - 1) ? 1.0f : 0.5f;

    // ---- preload: wm (x0-1 own row), wc (x0 own row), smem plane for x0
    float4 wm[3], wc[3];
    {
        int xmi = max(x0 - 1, 0);
        #pragma unroll
        for (int c = 0; c < 3; c++) {
            const float* p = base + c * S3;
            wm[c] = *reinterpret_cast<const float4*>(p + xmi * S2 + offyz);
            wc[c] = *reinterpret_cast<const float4*>(p + x0 * S2 + offyz);
            *reinterpret_cast<float4*>(&sp[0][c][yt + 1][z4]) = wc[c];
            if (yt == 0)
                *reinterpret_cast<float4*>(&sp[0][c][0][z4]) =
                    *reinterpret_cast<const float4*>(p + x0 * S2 + hoff_m);
            if (yt == 3)
                *reinterpret_cast<float4*>(&sp[0][c][5][z4]) =
                    *reinterpret_cast<const float4*>(p + x0 * S2 + hoff_p);
        }
    }
    __syncthreads();

    float sum0 = 0.0f, sum1 = 0.0f;

    #pragma unroll 2
    for (int xi = 0; xi < XSEG; xi++) {
        int x  = x0 + xi;
        int xn = (x == DD - 1) ? x : x + 1;
        float sx = (x == 0 || x == DD - 1) ? 1.0f : 0.5f;
        int cur = xi & 1, nxt = cur ^ 1;

        // load plane x+1 (compulsory) into regs + next smem buffer
        float4 wp[3];
        #pragma unroll
        for (int c = 0; c < 3; c++) {
            const float* p = base + c * S3 + xn * S2;
            wp[c] = *reinterpret_cast<const float4*>(p + offyz);
            *reinterpret_cast<float4*>(&sp[nxt][c][yt + 1][z4]) = wp[c];
            if (yt == 0)
                *reinterpret_cast<float4*>(&sp[nxt][c][0][z4]) =
                    *reinterpret_cast<const float4*>(p + hoff_m);
            if (yt == 3)
                *reinterpret_cast<float4*>(&sp[nxt][c][5][z4]) =
                    *reinterpret_cast<const float4*>(p + hoff_p);
        }

        // compute derivatives at plane x from regs + sp[cur]
        float dX[3][4], dY[3][4], dZ[3][4];
        #pragma unroll
        for (int c = 0; c < 3; c++) {
            float4 ym4 = *reinterpret_cast<const float4*>(&sp[cur][c][yt][z4]);
            float4 yp4 = *reinterpret_cast<const float4*>(&sp[cur][c][yt + 2][z4]);
            float zm = (zt > 0)  ? sp[cur][c][yt + 1][z4 - 1] : wc[c].x;
            float zp = (zt < 47) ? sp[cur][c][yt + 1][z4 + 4] : wc[c].w;

            float cz[6]  = {zm, wc[c].x, wc[c].y, wc[c].z, wc[c].w, zp};
            float xmv[4] = {wm[c].x, wm[c].y, wm[c].z, wm[c].w};
            float xpv[4] = {wp[c].x, wp[c].y, wp[c].z, wp[c].w};
            float ymv[4] = {ym4.x, ym4.y, ym4.z, ym4.w};
            float ypv[4] = {yp4.x, yp4.y, yp4.z, yp4.w};
            #pragma unroll
            for (int j = 0; j < 4; j++) {
                int z = z4 + j;
                float sz = (z == 0 || z == DD - 1) ? 1.0f : 0.5f;
                dX[c][j] = (xpv[j] - xmv[j]) * sx;
                dY[c][j] = (ypv[j] - ymv[j]) * sy;
                dZ[c][j] = (cz[j + 2] - cz[j]) * sz;
            }
        }

        #pragma unroll
        for (int j = 0; j < 4; j++) {
            float ux = dX[0][j], uy = dY[0][j], uz = dZ[0][j];
            float vx = dX[1][j], vy = dY[1][j], vz = dZ[1][j];
            float wx = dX[2][j], wy = dY[2][j], wz = dZ[2][j];

            float tr  = ux + vy + wz;
            float exy = 0.5f * (uy + vx);
            float exz = 0.5f * (uz + wx);
            float eyz = 0.5f * (vz + wy);

            float rt  = robust01(tr);
            float rxx = robust01(ux), ryy = robust01(vy), rzz = robust01(wz);
            float rxy = robust01(exy), rxz = robust01(exz), ryz = robust01(eyz);

            // 0.5*LAMBDA*rt^2 + MU*(diag^2 + 2*offdiag^2), LAMBDA=1, MU=0.5
            float energy = 0.5f * rt * rt
                         + 0.5f * (rxx * rxx + ryy * ryy + rzz * rzz
                                   + 2.0f * (rxy * rxy + rxz * rxz + ryz * ryz));

            float jac = (1.0f + ux) * ((1.0f + vy) * (1.0f + wz) - vz * wy)
                      - uy * (vx * (1.0f + wz) - vz * (1.0f + wx))
                      + uz * (vx * wy - (1.0f + vy) * (1.0f + wx));

            float val = energy + 0.1f * fmaxf(-jac, 0.0f);
            if (j & 1) sum1 += val; else sum0 += val;
        }

        // shift window; barrier protects sp[cur] reads vs next iter's writes
        #pragma unroll
        for (int c = 0; c < 3; c++) { wm[c] = wc[c]; wc[c] = wp[c]; }
        __syncthreads();
    }

    // ---- block reduction (double)
    double d = (double)sum0 + (double)sum1;
    #pragma unroll
    for (int o = 16; o > 0; o >>= 1)
        d += __shfl_down_sync(0xffffffffu, d, o);

    int tid = zt + yt * 48;             // 192 threads = 6 warps
    int w = tid >> 5, l = tid & 31;
    if (l == 0) ws[w] = d;
    __syncthreads();
    if (tid == 0) {
        double t = 0.0;
        #pragma unroll
        for (int i = 0; i < 6; i++) t += ws[i];
        g_part[bid] = t;
        __threadfence();
        unsigned ticket = atomicInc(&g_cnt, NBLK - 1);   // wraps to 0 -> replay-safe
        is_last = (ticket == NBLK - 1);
    }
    __syncthreads();

    // ---- last block folds all partials and writes the scalar
    if (is_last) {
        double s = 0.0;
        for (int i = tid; i < NBLK; i += 192)
            s += __ldcg(&g_part[i]);
        #pragma unroll
        for (int o = 16; o > 0; o >>= 1)
            s += __shfl_down_sync(0xffffffffu, s, o);
        if (l == 0) ws[w] = s;
        __syncthreads();
        if (tid == 0) {
            double t = 0.0;
            #pragma unroll
            for (int i = 0; i < 6; i++) t += ws[i];
            out[0] = (float)(t / NVOX);
        }
    }
}

extern "C" void kernel_launch(void* const* d_in, const int* in_sizes, int n_in,
                              void* d_out, int out_size) {
    const float* df = (const float*)d_in[0];
    float* out = (float*)d_out;
    dim3 blk(48, 4);
    elastic_kernel<<<NBLK, blk>>>(df, out);
}

// round 11
// speedup vs baseline: 2.0548x; 2.0548x over previous
#include <cuda_runtime.h>
#include <cuda_bf16.h>

// ElasticEnergyLossWithJacobian — GB300 sm_103a, round 9.
// R5 register-window design (no smem staging, no per-plane barrier) +
// fused last-block reduction + pointer-increment addressing + branch-free
// clamped halo offsets.

#define DD 192
#define S1 192
#define S2 (192*192)
#define S3 (192*192*192)
#define XSEG 16
#define NSEG (DD / XSEG)          // 12
#define NBLK (2 * NSEG * 48)      // 1152
#define NVOX (2.0*192.0*192.0*192.0)

__device__ double g_part[NBLK];
__device__ unsigned int g_cnt = 0;   // atomicInc wraps to 0 every launch

__device__ __forceinline__ float robust01(float x) {
    float a = fabsf(x);
    return (a <= 0.01f) ? 0.5f * x * x : 0.01f * (a - 0.005f);
}

__global__ __launch_bounds__(192) void elastic_kernel(const float* __restrict__ df,
                                                      float* __restrict__ out) {
    __shared__ double ws[6];
    __shared__ bool is_last;

    int bid   = blockIdx.x;
    int b     = bid / (NSEG * 48);
    int r     = bid % (NSEG * 48);
    int xseg  = r / 48;
    int ytile = r % 48;
    int yt = threadIdx.y;               // 0..3
    int zt = threadIdx.x;               // 0..47
    int y  = ytile * 4 + yt;
    int z4 = zt * 4;
    int x0 = xseg * XSEG;

    // Per-component pointers to (x0, y, z4); advance by S2 each x-step.
    const float* pc0 = df + (size_t)b * 3 * S3 + (size_t)x0 * S2 + y * S1 + z4;
    const float* pc1 = pc0 + S3;
    const float* pc2 = pc1 + S3;

    // Clamped constant offsets (branch-free halos).
    int dym = (y == 0      ? 0 : -S1);
    int dyp = (y == DD - 1 ? 0 :  S1);
    int dzm = (zt == 0  ? 0 : -1);       // clamped: reloads center.x at z=0
    int dzp = (zt == 47 ? 3 :  4);       // clamped: reloads center.w at z=191

    float sy = (y == 0 || y == DD - 1) ? 1.0f : 0.5f;
    float szv[4] = {0.5f, 0.5f, 0.5f, 0.5f};
    if (zt == 0)  szv[0] = 1.0f;
    if (zt == 47) szv[3] = 1.0f;

    // Register window: x-1 plane (wm) and x plane (wc) per component.
    float4 wm[3], wc[3];
    {
        int back = (x0 == 0) ? 0 : S2;
        wm[0] = *reinterpret_cast<const float4*>(pc0 - back);
        wm[1] = *reinterpret_cast<const float4*>(pc1 - back);
        wm[2] = *reinterpret_cast<const float4*>(pc2 - back);
        wc[0] = *reinterpret_cast<const float4*>(pc0);
        wc[1] = *reinterpret_cast<const float4*>(pc1);
        wc[2] = *reinterpret_cast<const float4*>(pc2);
    }

    float sum0 = 0.0f, sum1 = 0.0f;

    #pragma unroll 2
    for (int xi = 0; xi < XSEG; xi++) {
        int x = x0 + xi;
        int fwd = (x == DD - 1) ? 0 : S2;
        float sx = (x == 0 || x == DD - 1) ? 1.0f : 0.5f;

        const float* q[3] = {pc0, pc1, pc2};

        float4 wp[3], ym4[3], yp4[3];
        float zm[3], zp[3];
        #pragma unroll
        for (int c = 0; c < 3; c++) {
            wp[c]  = *reinterpret_cast<const float4*>(q[c] + fwd);
            ym4[c] = *reinterpret_cast<const float4*>(q[c] + dym);
            yp4[c] = *reinterpret_cast<const float4*>(q[c] + dyp);
            zm[c]  = q[c][dzm];
            zp[c]  = q[c][dzp];
        }

        float dX[3][4], dY[3][4], dZ[3][4];
        #pragma unroll
        for (int c = 0; c < 3; c++) {
            float cz[6]  = {zm[c], wc[c].x, wc[c].y, wc[c].z, wc[c].w, zp[c]};
            float xmv[4] = {wm[c].x, wm[c].y, wm[c].z, wm[c].w};
            float xpv[4] = {wp[c].x, wp[c].y, wp[c].z, wp[c].w};
            float ymv[4] = {ym4[c].x, ym4[c].y, ym4[c].z, ym4[c].w};
            float ypv[4] = {yp4[c].x, yp4[c].y, yp4[c].z, yp4[c].w};
            #pragma unroll
            for (int j = 0; j < 4; j++) {
                dX[c][j] = (xpv[j] - xmv[j]) * sx;
                dY[c][j] = (ypv[j] - ymv[j]) * sy;
                dZ[c][j] = (cz[j + 2] - cz[j]) * szv[j];
            }
        }

        #pragma unroll
        for (int j = 0; j < 4; j++) {
            float ux = dX[0][j], uy = dY[0][j], uz = dZ[0][j];
            float vx = dX[1][j], vy = dY[1][j], vz = dZ[1][j];
            float wx = dX[2][j], wy = dY[2][j], wz = dZ[2][j];

            float tr  = ux + vy + wz;
            float exy = 0.5f * (uy + vx);
            float exz = 0.5f * (uz + wx);
            float eyz = 0.5f * (vz + wy);

            float rt  = robust01(tr);
            float rxx = robust01(ux), ryy = robust01(vy), rzz = robust01(wz);
            float rxy = robust01(exy), rxz = robust01(exz), ryz = robust01(eyz);

            // 0.5*LAMBDA*rt^2 + MU*(diag^2 + 2*offdiag^2), LAMBDA=1, MU=0.5
            float energy = 0.5f * rt * rt
                         + 0.5f * (rxx * rxx + ryy * ryy + rzz * rzz
                                   + 2.0f * (rxy * rxy + rxz * rxz + ryz * ryz));

            float jac = (1.0f + ux) * ((1.0f + vy) * (1.0f + wz) - vz * wy)
                      - uy * (vx * (1.0f + wz) - vz * (1.0f + wx))
                      + uz * (vx * wy - (1.0f + vy) * (1.0f + wx));

            float val = energy + 0.1f * fmaxf(-jac, 0.0f);
            if (j & 1) sum1 += val; else sum0 += val;
        }

        // shift window, advance pointers
        #pragma unroll
        for (int c = 0; c < 3; c++) { wm[c] = wc[c]; wc[c] = wp[c]; }
        pc0 += S2; pc1 += S2; pc2 += S2;
    }

    // ---- block reduction (double)
    double d = (double)sum0 + (double)sum1;
    #pragma unroll
    for (int o = 16; o > 0; o >>= 1)
        d += __shfl_down_sync(0xffffffffu, d, o);

    int tid = zt + yt * 48;             // 192 threads = 6 warps
    int w = tid >> 5, l = tid & 31;
    if (l == 0) ws[w] = d;
    __syncthreads();
    if (tid == 0) {
        double t = 0.0;
        #pragma unroll
        for (int i = 0; i < 6; i++) t += ws[i];
        g_part[bid] = t;
        __threadfence();
        unsigned ticket = atomicInc(&g_cnt, NBLK - 1);   // wraps -> replay-safe
        is_last = (ticket == NBLK - 1);
    }
    __syncthreads();

    // ---- last block folds all partials and writes the scalar
    if (is_last) {
        double s = 0.0;
        for (int i = tid; i < NBLK; i += 192)
            s += __ldcg(&g_part[i]);
        #pragma unroll
        for (int o = 16; o > 0; o >>= 1)
            s += __shfl_down_sync(0xffffffffu, s, o);
        if (l == 0) ws[w] = s;
        __syncthreads();
        if (tid == 0) {
            double t = 0.0;
            #pragma unroll
            for (int i = 0; i < 6; i++) t += ws[i];
            out[0] = (float)(t / NVOX);
        }
    }
}

extern "C" void kernel_launch(void* const* d_in, const int* in_sizes, int n_in,
                              void* d_out, int out_size) {
    const float* df = (const float*)d_in[0];
    float* out = (float*)d_out;
    dim3 blk(48, 4);
    elastic_kernel<<<NBLK, blk>>>(df, out);
}